// round 9
// baseline (speedup 1.0000x reference)
#include <cuda_runtime.h>
#include <cuda_bf16.h>
#include <cstdint>

// ---------------------------------------------------------------------------
// SpatialNonIntersectionAxiom — two-phase sparse formulation.
// out[0]=loss, out[1..1+E^2)=violation_mask, out[1+E^2..1+2E^2)=scores (f32).
//
// Graph: memset(bk) -> memset(planes) -> prep -> phase1(mask/count/gate)
//        -> phase2(dense segment math + scatter + final loss).
// All cross-block accumulation is integer (fixed-point 2^-40) -> outputs are
// bit-deterministic across graph replays despite nondeterministic atomics.
// ---------------------------------------------------------------------------

#define MAXE  8192
#define MAXB  16
#define BLK   256
#define CHNK  96
#define CAP   (2 * 1024 * 1024)
#define P2B   256

// Batch-sorted per-edge tables (written by prep; __device__: no allocs)
__device__ float4 g_sT0[MAXB * MAXE]; // midx, midy, hh=half+0.075, packed(s<<12|d)
__device__ float4 g_sT1[MAXB * MAXE]; // psx, psy, d1x, d1y
__device__ float4 g_sT2[MAXB * MAXE]; // dda, sq(clamped), rinv=1/sq, edgeIdx bits
__device__ unsigned int g_nzList[CAP];

struct Bookkeep {
    unsigned long long totQ;   // fixed-point 2^-40 loss sum
    unsigned long long totC;   // candidate count (n_pairs)
    unsigned int nz;           // gated-pair list length
    unsigned int done2;        // phase-2 finished-block counter
    int bcnt[MAXB];            // per-batch sorted-table lengths
};
__device__ Bookkeep g_bk;

__global__ void prep_kernel(const float* __restrict__ pos,
                            const int* __restrict__ ei,
                            int E, int N, int nodes) {
    int e = blockIdx.x * blockDim.x + threadIdx.x;
    if (e >= E) return;
    int s = ei[e];
    int d = ei[E + e];
    s = min(max(s, 0), nodes - 1);
    d = min(max(d, 0), nodes - 1);
    float psx = pos[2 * s],  psy = pos[2 * s + 1];
    float pdx = pos[2 * d],  pdy = pos[2 * d + 1];
    float d1x = pdx - psx,   d1y = pdy - psy;
    float rawsq = d1x * d1x + d1y * d1y;
    float sq    = fmaxf(rawsq, 1e-12f);
    float rinv  = __fdiv_rn(1.0f, sq);
    float half  = __fsqrt_rn(rawsq) * 0.5f;
    float midx  = (psx + pdx) * 0.5f;
    float midy  = (psy + pdy) * 0.5f;
    float dda   = d1x * psx + d1y * psy;
    int b = min(s / N, MAXB - 1);
    unsigned int packed = (((unsigned int)s & 0xFFFu) << 12)
                        | ((unsigned int)d & 0xFFFu);
    int p = atomicAdd(&g_bk.bcnt[b], 1);
    if (p < MAXE) {
        int o = b * MAXE + p;
        g_sT0[o] = make_float4(midx, midy, half + 0.075f,
                               __uint_as_float(packed));
        g_sT1[o] = make_float4(psx, psy, d1x, d1y);
        g_sT2[o] = make_float4(dda, sq, rinv, __int_as_float(e));
    }
}

// Phase 1: unordered same-batch pair enumeration; count mask; append gated.
__global__ void __launch_bounds__(BLK)
phase1_kernel(int E) {
    const int b = blockIdx.y;
    const int L = min(g_bk.bcnt[b], MAXE);
    const float4* __restrict__ T0 = g_sT0 + b * MAXE;
    const int lane = threadIdx.x & 31;

    unsigned int cnt = 0u;

    for (int ki = blockIdx.x; ki < L; ki += CHNK) {
        float4 r0 = T0[ki];                       // broadcast (warp-uniform)
        unsigned int pr = __float_as_uint(r0.w);
        unsigned int rs = pr >> 12, rd = pr & 0xFFFu;
        for (int base = ki + 1; base < L; base += BLK) {
            int kj = base + threadIdx.x;
            bool valid = (kj < L);
            bool gated = false;
            if (valid) {
                float4 q0 = T0[kj];               // coalesced LDG.128
                unsigned int pq = __float_as_uint(q0.w);
                unsigned int qs = pq >> 12, qd = pq & 0xFFFu;
                bool shares = (rs == qs) | (rs == qd) | (rd == qs) | (rd == qd);
                float dx = r0.x - q0.x;
                float dy = r0.y - q0.y;
                float d2 = dx * dx + dy * dy;
                float reach = r0.z + q0.z;        // half_i+half_j+0.15
                bool maskok = (!shares) && (d2 < reach * reach);
                cnt += maskok ? 1u : 0u;
                float gr = reach - 0.1488f;       // half_i+half_j+0.0012
                gated = (!shares) && (d2 < gr * gr);
            }
            // Warp-aggregated append of gated pairs
            unsigned int m = __ballot_sync(0xffffffffu, gated);
            if (m) {
                int leader = __ffs(m) - 1;
                unsigned int bpos = 0u;
                if (lane == leader)
                    bpos = atomicAdd(&g_bk.nz, (unsigned int)__popc(m));
                bpos = __shfl_sync(0xffffffffu, bpos, leader);
                if (gated) {
                    unsigned int pos = bpos +
                        (unsigned int)__popc(m & ((1u << lane) - 1u));
                    if (pos < CAP)
                        g_nzList[pos] = ((unsigned int)b << 26)
                                      | ((unsigned int)ki << 13)
                                      | (unsigned int)kj;
                }
            }
        }
    }

    // Reduce candidate count -> totC
#pragma unroll
    for (int o = 16; o; o >>= 1)
        cnt += __shfl_xor_sync(0xffffffffu, cnt, o);
    __shared__ unsigned int sC[BLK / 32];
    int w = threadIdx.x >> 5;
    if (lane == 0) sC[w] = cnt;
    __syncthreads();
    if (threadIdx.x == 0) {
        unsigned int c = 0u;
#pragma unroll
        for (int k = 0; k < BLK / 32; k++) c += sC[k];
        if (c) atomicAdd(&g_bk.totC, (unsigned long long)c);
    }
}

// Phase 2: dense segment-distance over the gated list; scatter nonzeros;
// last block writes out[0].
__global__ void __launch_bounds__(BLK)
phase2_kernel(float* __restrict__ out, int E, int writeBig) {
    float* __restrict__ outM = out + 1;
    float* __restrict__ outS = out + 1 + (size_t)E * (size_t)E;

    const unsigned int nz = min(g_bk.nz, (unsigned int)CAP);
    unsigned long long accQ = 0ull;

    for (unsigned int idx = blockIdx.x * BLK + threadIdx.x; idx < nz;
         idx += gridDim.x * BLK) {
        unsigned int pk = g_nzList[idx];
        int b  = (int)(pk >> 26);
        int ki = (int)((pk >> 13) & 0x1FFFu);
        int kj = (int)(pk & 0x1FFFu);
        int o  = b * MAXE;
        float4 r1 = g_sT1[o + ki], q1 = g_sT1[o + kj];
        float4 r2 = g_sT2[o + ki], q2 = g_sT2[o + kj];
        int re = __float_as_int(r2.w);
        int qe = __float_as_int(q2.w);
        bool sw = re > qe;   // orient: i = smaller original edge index
        float4 iA = sw ? q1 : r1, jA = sw ? r1 : q1;
        float iDda = sw ? q2.x : r2.x, jDda = sw ? r2.x : q2.x;
        float A    = sw ? q2.y : r2.y, Ee   = sw ? r2.y : q2.y;
        float rA   = sw ? q2.z : r2.z, rE   = sw ? r2.z : q2.z;

        float bb = iA.z * jA.z + iA.w * jA.w;
        float cc = iDda - (iA.z * jA.x + iA.w * jA.y);
        float ff = (iA.x * jA.z + iA.y * jA.w) - jDda;
        float denom = fmaxf(A * Ee - bb * bb, 1e-12f);
        float s = (bb * ff - cc * Ee) * __frcp_rn(denom);
        s = fminf(fmaxf(s, 0.0f), 1.0f);
        float t = fminf(fmaxf((bb * s + ff) * rE, 0.0f), 1.0f);
        s = fminf(fmaxf((bb * t - cc) * rA, 0.0f), 1.0f);
        float cax = iA.x + s * iA.z;
        float cay = iA.y + s * iA.w;
        float cbx = jA.x + t * jA.z;
        float cby = jA.y + t * jA.w;
        float ddx = cax - cbx, ddy = cay - cby;
        float dmsq = ddx * ddx + ddy * ddy;
        if (dmsq < 1.2e-6f) {                     // only here pay the sqrt
            float dmin = __fsqrt_rn(dmsq);
            float pl = 0.001f - dmin;
            if (pl > 0.0f) {
                accQ += (unsigned long long)
                    __double2ll_rn((double)pl * 1099511627776.0);
                if (writeBig) {
                    int i = sw ? qe : re, j = sw ? re : qe;
                    size_t off = (size_t)i * (size_t)E + (size_t)j;
                    outM[off] = 1.0f;
                    outS[off] = pl;
                }
            }
        }
    }

    // Reduce loss -> totQ; last block computes out[0]
#pragma unroll
    for (int o = 16; o; o >>= 1)
        accQ += __shfl_xor_sync(0xffffffffu, accQ, o);
    __shared__ unsigned long long sQ[BLK / 32];
    int w = threadIdx.x >> 5;
    if ((threadIdx.x & 31) == 0) sQ[w] = accQ;
    __syncthreads();
    if (threadIdx.x == 0) {
        unsigned long long q = 0ull;
#pragma unroll
        for (int k = 0; k < BLK / 32; k++) q += sQ[k];
        if (q) atomicAdd(&g_bk.totQ, q);
        __threadfence();
        unsigned int old = atomicAdd(&g_bk.done2, 1u);
        if (old == gridDim.x - 1u) {
            unsigned long long tq = atomicAdd(&g_bk.totQ, 0ull);
            unsigned long long tc = atomicAdd(&g_bk.totC, 0ull);
            double sum = (double)tq * (1.0 / 1099511627776.0);
            unsigned long long n = tc ? tc : 1ull;
            out[0] = (float)(sum / (double)n);
        }
    }
}

extern "C" void kernel_launch(void* const* d_in, const int* in_sizes, int n_in,
                              void* d_out, int out_size) {
    const float* pos = (const float*)d_in[0];
    // d_in[1] = adjacency: unused by the reference computation
    const int*   ei  = (const int*)d_in[2];

    int E     = in_sizes[2] / 2;
    int nodes = in_sizes[0] / 2;
    int N     = in_sizes[1] / nodes;
    int B     = min((nodes + N - 1) / N, MAXB);

    long long need = 1ll + 2ll * (long long)E * (long long)E;
    int writeBig = ((long long)out_size >= need) ? 1 : 0;

    float* out = (float*)d_out;

    // 1) Clear bookkeeping
    void* bkPtr = nullptr;
    cudaGetSymbolAddress(&bkPtr, g_bk);
    cudaMemsetAsync(bkPtr, 0, sizeof(Bookkeep));

    // 2) Zero-fill output planes (DRAM-write-rate driver fill)
    if (writeBig) {
        cudaMemsetAsync(out + 1, 0,
                        2ull * (size_t)E * (size_t)E * sizeof(float));
    } else if (out_size > 1) {
        cudaMemsetAsync(out + 1, 0, ((size_t)out_size - 1) * sizeof(float));
    }

    // 3) Batch-sorted tables
    prep_kernel<<<(E + 127) / 128, 128>>>(pos, ei, E, N, nodes);

    // 4) Mask count + gated-pair compaction (no div/sqrt)
    dim3 g1(CHNK, B);
    phase1_kernel<<<g1, BLK>>>(E);

    // 5) Dense segment math over compact list + scatter + final loss
    phase2_kernel<<<P2B, BLK>>>(out, E, writeBig);
}

// round 10
// speedup vs baseline: 1.6193x; 1.6193x over previous
#include <cuda_runtime.h>
#include <cuda_bf16.h>
#include <cstdint>

// ---------------------------------------------------------------------------
// SpatialNonIntersectionAxiom — single branchless SMEM-staged compute.
// out[0]=loss, out[1..1+E^2)=violation_mask, out[1+E^2..1+2E^2)=scores (f32).
//
// Graph: memset(bk) -> memset(planes) -> prep -> compute.
// Compute enumerates unordered same-batch pairs from SMEM, does the full
// segment-distance math BRANCHLESS (rcp instead of div, sqrt only behind the
// rare dmin^2 < eps^2 test), scatters rare nonzeros, and the last block
// writes out[0]. Integer (fixed-point 2^-40) accumulation -> bit-
// deterministic outputs across graph replays.
// ---------------------------------------------------------------------------

#define MAXE  8192
#define MAXB  16
#define BLK   256
#define CHNK  96
#define SMAXL 768

// Batch-major per-edge tables (written by prep; __device__: no allocs)
__device__ float4 g_tP[MAXB * MAXE]; // psx, psy, d1x, d1y
__device__ float4 g_tM[MAXB * MAXE]; // midx, midy, hh=half+0.075, packed(s<<12|d)
__device__ float4 g_tD[MAXB * MAXE]; // dda, sq(clamped), rinv=1/sq, edgeIdx bits

struct Bookkeep {
    unsigned long long totQ;   // fixed-point 2^-40 loss sum
    unsigned long long totC;   // candidate count (n_pairs)
    unsigned int done;         // finished-block counter
    unsigned int pad;
    int bcnt[MAXB];            // per-batch table lengths
};
__device__ Bookkeep g_bk;

__global__ void prep_kernel(const float* __restrict__ pos,
                            const int* __restrict__ ei,
                            int E, int N, int nodes) {
    int e = blockIdx.x * blockDim.x + threadIdx.x;
    if (e >= E) return;
    int s = ei[e];
    int d = ei[E + e];
    s = min(max(s, 0), nodes - 1);
    d = min(max(d, 0), nodes - 1);
    float psx = pos[2 * s],  psy = pos[2 * s + 1];
    float pdx = pos[2 * d],  pdy = pos[2 * d + 1];
    float d1x = pdx - psx,   d1y = pdy - psy;
    float rawsq = d1x * d1x + d1y * d1y;
    float sq    = fmaxf(rawsq, 1e-12f);
    float rinv  = __fdiv_rn(1.0f, sq);
    float half  = __fsqrt_rn(rawsq) * 0.5f;
    float midx  = (psx + pdx) * 0.5f;
    float midy  = (psy + pdy) * 0.5f;
    float dda   = d1x * psx + d1y * psy;
    int b = min(s / N, MAXB - 1);
    unsigned int packed = (((unsigned int)s & 0xFFFu) << 12)
                        | ((unsigned int)d & 0xFFFu);

    // Warp-aggregated list append: one atomic per distinct batch per warp.
    unsigned int am   = __activemask();
    unsigned int grp  = __match_any_sync(am, b);
    int leader        = __ffs(grp) - 1;
    int myrank        = __popc(grp & ((1u << (threadIdx.x & 31)) - 1u));
    int p0 = 0;
    if ((threadIdx.x & 31) == leader)
        p0 = atomicAdd(&g_bk.bcnt[b], __popc(grp));
    p0 = __shfl_sync(am, p0, leader);
    int p = p0 + myrank;

    if (p < MAXE) {
        int o = b * MAXE + p;
        g_tP[o] = make_float4(psx, psy, d1x, d1y);
        g_tM[o] = make_float4(midx, midy, half + 0.075f,
                              __uint_as_float(packed));
        g_tD[o] = make_float4(dda, sq, rinv, __int_as_float(e));
    }
}

// grid = (CHNK, B). SMEM-staged, branchless unordered-pair enumeration.
__global__ void __launch_bounds__(BLK)
compute_kernel(float* __restrict__ out, int E, int writeBig, int totBlocks) {
    __shared__ float4 sP[SMAXL];
    __shared__ float4 sM[SMAXL];
    __shared__ float4 sD[SMAXL];

    const int b = blockIdx.y;
    const int c = blockIdx.x;
    const int L = min(g_bk.bcnt[b], MAXE);
    const bool inSmem = (L <= SMAXL);

    const float4* __restrict__ P = inSmem ? sP : (g_tP + b * MAXE);
    const float4* __restrict__ M = inSmem ? sM : (g_tM + b * MAXE);
    const float4* __restrict__ D = inSmem ? sD : (g_tD + b * MAXE);

    if (inSmem) {
        for (int k = threadIdx.x; k < L; k += BLK) {
            int o = b * MAXE + k;
            sP[k] = g_tP[o]; sM[k] = g_tM[o]; sD[k] = g_tD[o];
        }
        __syncthreads();
    }

    float* __restrict__ outMk = out + 1;
    float* __restrict__ outSc = out + 1 + (size_t)E * (size_t)E;

    unsigned long long accQ = 0ull;
    unsigned int       cnt  = 0u;

    for (int ki = c; ki < L; ki += CHNK) {
        float4 rP = P[ki], rM = M[ki], rD = D[ki];
        unsigned int pr = __float_as_uint(rM.w);
        unsigned int rs = pr >> 12, rd = pr & 0xFFFu;
        int re = __float_as_int(rD.w);

        for (int kj = ki + 1 + threadIdx.x; kj < L; kj += BLK) {
            float4 qM = M[kj];
            float4 qP = P[kj];
            float4 qD = D[kj];
            unsigned int pq = __float_as_uint(qM.w);
            unsigned int qs = pq >> 12, qd = pq & 0xFFFu;
            bool shares = (rs == qs) | (rs == qd) | (rd == qs) | (rd == qd);
            float dx = rM.x - qM.x;
            float dy = rM.y - qM.y;
            float d2 = dx * dx + dy * dy;
            float reach = rM.z + qM.z;            // half_i+half_j+0.15
            bool maskok = (!shares) && (d2 < reach * reach);
            cnt += maskok ? 1u : 0u;

            // Branchless segment-distance (orient i = smaller edge index)
            int qe = __float_as_int(qD.w);
            bool sw = re > qe;
            float iAx = sw ? qP.x : rP.x, iAy = sw ? qP.y : rP.y;
            float iAz = sw ? qP.z : rP.z, iAw = sw ? qP.w : rP.w;
            float jAx = sw ? rP.x : qP.x, jAy = sw ? rP.y : qP.y;
            float jAz = sw ? rP.z : qP.z, jAw = sw ? rP.w : qP.w;
            float iDd = sw ? qD.x : rD.x, jDd = sw ? rD.x : qD.x;
            float A   = sw ? qD.y : rD.y, Ee  = sw ? rD.y : qD.y;
            float rA  = sw ? qD.z : rD.z, rE  = sw ? rD.z : qD.z;

            float bb = iAz * jAz + iAw * jAw;
            float cc = iDd - (iAz * jAx + iAw * jAy);
            float ff = (iAx * jAz + iAy * jAw) - jDd;
            float denom = fmaxf(A * Ee - bb * bb, 1e-12f);
            float s = (bb * ff - cc * Ee) * __frcp_rn(denom);
            s = fminf(fmaxf(s, 0.0f), 1.0f);
            float t = fminf(fmaxf((bb * s + ff) * rE, 0.0f), 1.0f);
            s = fminf(fmaxf((bb * t - cc) * rA, 0.0f), 1.0f);
            float cax = iAx + s * iAz;
            float cay = iAy + s * iAw;
            float cbx = jAx + t * jAz;
            float cby = jAy + t * jAw;
            float ddx = cax - cbx, ddy = cay - cby;
            float dmsq = ddx * ddx + ddy * ddy;

            if (maskok && dmsq < 1.01e-6f) {      // rare: real violations
                float dmin = __fsqrt_rn(dmsq);
                float pl = 0.001f - dmin;
                if (pl > 0.0f) {
                    accQ += (unsigned long long)
                        __double2ll_rn((double)pl * 1099511627776.0);
                    if (writeBig) {
                        int i = sw ? qe : re, j = sw ? re : qe;
                        size_t off = (size_t)i * (size_t)E + (size_t)j;
                        outMk[off] = 1.0f;
                        outSc[off] = pl;
                    }
                }
            }
        }
    }

    // Block reduction -> global totals; last block writes out[0]
#pragma unroll
    for (int o = 16; o; o >>= 1) {
        accQ += __shfl_xor_sync(0xffffffffu, accQ, o);
        cnt  += __shfl_xor_sync(0xffffffffu, cnt,  o);
    }
    __shared__ unsigned long long rQ[BLK / 32];
    __shared__ unsigned int       rC[BLK / 32];
    int w = threadIdx.x >> 5;
    if ((threadIdx.x & 31) == 0) { rQ[w] = accQ; rC[w] = cnt; }
    __syncthreads();
    if (threadIdx.x == 0) {
        unsigned long long q = 0ull; unsigned int cc2 = 0u;
#pragma unroll
        for (int k = 0; k < BLK / 32; k++) { q += rQ[k]; cc2 += rC[k]; }
        if (q) atomicAdd(&g_bk.totQ, q);
        if (cc2) atomicAdd(&g_bk.totC, (unsigned long long)cc2);
        __threadfence();
        unsigned int old = atomicAdd(&g_bk.done, 1u);
        if (old == (unsigned int)totBlocks - 1u) {
            unsigned long long tq = atomicAdd(&g_bk.totQ, 0ull);
            unsigned long long tc = atomicAdd(&g_bk.totC, 0ull);
            double sum = (double)tq * (1.0 / 1099511627776.0);
            unsigned long long n = tc ? tc : 1ull;
            out[0] = (float)(sum / (double)n);
        }
    }
}

extern "C" void kernel_launch(void* const* d_in, const int* in_sizes, int n_in,
                              void* d_out, int out_size) {
    const float* pos = (const float*)d_in[0];
    // d_in[1] = adjacency: unused by the reference computation
    const int*   ei  = (const int*)d_in[2];

    int E     = in_sizes[2] / 2;
    int nodes = in_sizes[0] / 2;
    int N     = in_sizes[1] / nodes;
    int B     = min((nodes + N - 1) / N, MAXB);

    long long need = 1ll + 2ll * (long long)E * (long long)E;
    int writeBig = ((long long)out_size >= need) ? 1 : 0;

    float* out = (float*)d_out;

    // 1) Clear bookkeeping
    void* bkPtr = nullptr;
    cudaGetSymbolAddress(&bkPtr, g_bk);
    cudaMemsetAsync(bkPtr, 0, sizeof(Bookkeep));

    // 2) Zero-fill output planes (DRAM-write-rate driver fill)
    if (writeBig) {
        cudaMemsetAsync(out + 1, 0,
                        2ull * (size_t)E * (size_t)E * sizeof(float));
    } else if (out_size > 1) {
        cudaMemsetAsync(out + 1, 0, ((size_t)out_size - 1) * sizeof(float));
    }

    // 3) Batch-major tables (warp-aggregated atomics)
    prep_kernel<<<(E + 127) / 128, 128>>>(pos, ei, E, N, nodes);

    // 4) Branchless SMEM-staged pair compute + scatter + final loss
    dim3 grid(CHNK, B);
    compute_kernel<<<grid, BLK>>>(out, E, writeBig, CHNK * B);
}